// round 1
// baseline (speedup 1.0000x reference)
#include <cuda_runtime.h>
#include <cuda_bf16.h>

// Problem constants (fixed by the dataset)
#define NN 50000
#define EE 800000
#define GG 64
#define HH 128
#define OO 10

// ---------------- static device scratch ----------------
__device__ float g_bufA[NN * HH];
__device__ float g_bufB[NN * HH];
__device__ float g_agg[NN * HH];
__device__ int   g_count[NN + 1];
__device__ int   g_rowptr[NN + 1];
__device__ int   g_cursor[NN];
__device__ int   g_col[EE];
__device__ int   g_cntg[GG];
__device__ int   g_gstart[GG + 1];
__device__ float g_inv[GG];
__device__ float g_pmax[GG * HH];
__device__ float g_psum[GG * HH];
__device__ float g_emb[GG * 2 * HH];
__device__ int   g_idx64;

// ---------------- index dtype handling ----------------
__device__ __forceinline__ int idx_at(const void* p, long long i) {
    if (g_idx64) return (int)((const long long*)p)[i];
    return ((const int*)p)[i];
}

__global__ void detect_idx_kernel(const void* ei, int n) {
    // If the data is int64, the first few 8-byte words are all in [0, n).
    // If it is int32, an 8-byte read aliases two entries -> almost surely >= 2^32.
    const long long* p = (const long long*)ei;
    int ok = 1;
    for (int i = 0; i < 4; i++) {
        long long v = p[i];
        if (v < 0 || v >= (long long)n) ok = 0;
    }
    g_idx64 = ok;
}

// ---------------- setup kernels ----------------
__global__ void zero_misc_kernel(int n) {
    int stride = gridDim.x * blockDim.x;
    int i = blockIdx.x * blockDim.x + threadIdx.x;
    for (int k = i; k < n + 1; k += stride) g_count[k] = 0;
    for (int k = i; k < GG; k += stride) g_cntg[k] = 0;
    for (int k = i; k < GG * 2 * HH; k += stride) g_emb[k] = 0.f;
}

__global__ void hist_edges_kernel(const void* ei, int E) {
    int e = blockIdx.x * blockDim.x + threadIdx.x;
    if (e < E) {
        int d = idx_at(ei, (long long)E + e);
        atomicAdd(&g_count[d], 1);
    }
}

__global__ void hist_nodes_kernel(const void* batch, int n) {
    int i = blockIdx.x * blockDim.x + threadIdx.x;
    if (i < n) {
        int g = idx_at(batch, i);
        atomicAdd(&g_cntg[g], 1);
    }
}

__global__ void scan_rows_kernel(int n) {
    __shared__ int ssum[1024];
    int t = threadIdx.x;
    int C = (n + 1023) / 1024;
    int c0 = t * C;
    int c1 = min(c0 + C, n);
    int s = 0;
    for (int i = c0; i < c1; i++) s += g_count[i];
    ssum[t] = s;
    __syncthreads();
    for (int off = 1; off < 1024; off <<= 1) {
        int v = (t >= off) ? ssum[t - off] : 0;
        __syncthreads();
        ssum[t] += v;
        __syncthreads();
    }
    int run = (t == 0) ? 0 : ssum[t - 1];
    for (int i = c0; i < c1; i++) {
        g_rowptr[i] = run;
        g_cursor[i] = run;
        run += g_count[i];
    }
    if (c0 < n && c1 == n) g_rowptr[n] = run;
}

__global__ void scatter_kernel(const void* ei, int E) {
    int e = blockIdx.x * blockDim.x + threadIdx.x;
    if (e < E) {
        int d = idx_at(ei, (long long)E + e);
        int s = idx_at(ei, e);
        int pos = atomicAdd(&g_cursor[d], 1);
        g_col[pos] = s;
    }
}

__global__ void graph_offsets_kernel() {
    if (threadIdx.x == 0 && blockIdx.x == 0) {
        int run = 0;
        for (int g = 0; g < GG; g++) {
            g_gstart[g] = run;
            run += g_cntg[g];
            g_inv[g] = 1.0f / (float)max(g_cntg[g], 1);
        }
        g_gstart[GG] = run;
    }
}

// ---------------- SpMM: agg[d] = sum_{e: dst==d} h[src[e]] ----------------
__global__ void spmm_kernel(const float* __restrict__ hin, float* __restrict__ agg) {
    int d = blockIdx.x;
    int t = threadIdx.x;  // 128 = feature
    int s = g_rowptr[d];
    int e = g_rowptr[d + 1];
    float a0 = 0.f, a1 = 0.f, a2 = 0.f, a3 = 0.f;
    int i = s;
    for (; i + 3 < e; i += 4) {
        int c0 = g_col[i + 0];
        int c1 = g_col[i + 1];
        int c2 = g_col[i + 2];
        int c3 = g_col[i + 3];
        a0 += hin[c0 * HH + t];
        a1 += hin[c1 * HH + t];
        a2 += hin[c2 * HH + t];
        a3 += hin[c3 * HH + t];
    }
    for (; i < e; i++) a0 += hin[g_col[i] * HH + t];
    agg[d * HH + t] = (a0 + a1) + (a2 + a3);
}

// ---------------- fused dual GEMM + bias + relu ----------------
// C[i][j] = relu( sum_k A0[i][k]*B0[j][k] + sum_k A1[i][k]*B1[j][k] + bias[j] )
// A0/A1: [N,128] row-major.  B0/B1: [128,128] row-major (out, k).
__global__ void __launch_bounds__(256) gemm_dual_kernel(
    const float* __restrict__ A0, const float* __restrict__ A1,
    const float* __restrict__ B0, const float* __restrict__ B1,
    const float* __restrict__ bias, float* __restrict__ C, int n)
{
    __shared__ float As[16][128];
    __shared__ float Bs[16][128];
    int tid = threadIdx.x;
    int row0 = blockIdx.x * 128;
    int tx = tid & 15;       // output-col group
    int ty = tid >> 4;       // row group
    int aQuad = tid & 3;     // k quad within 16
    int aRow = tid >> 2;     // 0..63

    float acc[8][8];
#pragma unroll
    for (int m = 0; m < 8; m++)
#pragma unroll
        for (int nn = 0; nn < 8; nn++) acc[m][nn] = 0.f;

    for (int kt = 0; kt < 16; kt++) {
        const float* A = (kt < 8) ? A0 : A1;
        const float* B = (kt < 8) ? B0 : B1;
        int kbase = (kt & 7) * 16;
        // A tile -> As[k][row]
#pragma unroll
        for (int h = 0; h < 2; h++) {
            int r = aRow + 64 * h;
            int grow = row0 + r;
            float4 v = make_float4(0.f, 0.f, 0.f, 0.f);
            if (grow < n) v = *(const float4*)&A[(size_t)grow * 128 + kbase + aQuad * 4];
            As[aQuad * 4 + 0][r] = v.x;
            As[aQuad * 4 + 1][r] = v.y;
            As[aQuad * 4 + 2][r] = v.z;
            As[aQuad * 4 + 3][r] = v.w;
        }
        // B tile -> Bs[k][j]
#pragma unroll
        for (int h = 0; h < 2; h++) {
            int j = aRow + 64 * h;
            float4 w = *(const float4*)&B[(size_t)j * 128 + kbase + aQuad * 4];
            Bs[aQuad * 4 + 0][j] = w.x;
            Bs[aQuad * 4 + 1][j] = w.y;
            Bs[aQuad * 4 + 2][j] = w.z;
            Bs[aQuad * 4 + 3][j] = w.w;
        }
        __syncthreads();
#pragma unroll
        for (int kk = 0; kk < 16; kk++) {
            float4 av0 = *(const float4*)&As[kk][ty * 8];
            float4 av1 = *(const float4*)&As[kk][ty * 8 + 4];
            float4 bv0 = *(const float4*)&Bs[kk][tx * 8];
            float4 bv1 = *(const float4*)&Bs[kk][tx * 8 + 4];
            float a[8] = {av0.x, av0.y, av0.z, av0.w, av1.x, av1.y, av1.z, av1.w};
            float b[8] = {bv0.x, bv0.y, bv0.z, bv0.w, bv1.x, bv1.y, bv1.z, bv1.w};
#pragma unroll
            for (int m = 0; m < 8; m++)
#pragma unroll
                for (int nn = 0; nn < 8; nn++) acc[m][nn] += a[m] * b[nn];
        }
        __syncthreads();
    }
    // epilogue: bias + relu
#pragma unroll
    for (int m = 0; m < 8; m++) {
        int row = row0 + ty * 8 + m;
        if (row < n) {
#pragma unroll
            for (int nn = 0; nn < 8; nn++) {
                int col = tx * 8 + nn;
                float v = acc[m][nn] + bias[col];
                C[(size_t)row * 128 + col] = fmaxf(v, 0.f);
            }
        }
    }
}

// ---------------- pooling (deterministic: one block per graph) ----------------
__global__ void pool_kernel(const float* __restrict__ h) {
    int g = blockIdx.x;
    int t = threadIdx.x;  // 128
    int n0 = g_gstart[g];
    int n1 = g_gstart[g + 1];
    float mx0 = 0.f, mx1 = 0.f, sm0 = 0.f, sm1 = 0.f;
    int i = n0;
    for (; i + 1 < n1; i += 2) {
        float v0 = h[(size_t)i * HH + t];
        float v1 = h[(size_t)(i + 1) * HH + t];
        mx0 = fmaxf(mx0, v0);
        mx1 = fmaxf(mx1, v1);
        sm0 += v0;
        sm1 += v1;
    }
    if (i < n1) {
        float v = h[(size_t)i * HH + t];
        mx0 = fmaxf(mx0, v);
        sm0 += v;
    }
    g_pmax[g * HH + t] = fmaxf(mx0, mx1);
    g_psum[g * HH + t] = sm0 + sm1;
}

__global__ void pool_accum_kernel() {
    int idx = blockIdx.x * blockDim.x + threadIdx.x;  // GG*HH threads
    if (idx < GG * HH) {
        int g = idx >> 7;
        int f = idx & 127;
        g_emb[g * 256 + f] += g_pmax[idx];
        g_emb[g * 256 + 128 + f] += g_psum[idx] * g_inv[g];
    }
}

// ---------------- MLP head + output of graph_emb ----------------
__global__ void mlp_kernel(const float* __restrict__ W1, const float* __restrict__ b1,
                           const float* __restrict__ W2, const float* __restrict__ b2,
                           const float* __restrict__ W3, const float* __restrict__ b3,
                           float* __restrict__ graphout, float* __restrict__ logits)
{
    __shared__ float in[256];
    __shared__ float z1[128];
    __shared__ float z2[64];
    int g = blockIdx.x;
    int t = threadIdx.x;  // 128
    in[t] = g_emb[g * 256 + t];
    in[t + 128] = g_emb[g * 256 + 128 + t];
    graphout[g * 256 + t] = in[t];
    graphout[g * 256 + 128 + t] = in[t + 128];
    __syncthreads();
    {
        float a = b1[t];
        const float* w = &W1[(size_t)t * 256];
#pragma unroll 8
        for (int k = 0; k < 256; k++) a += in[k] * w[k];
        z1[t] = fmaxf(a, 0.f);
    }
    __syncthreads();
    if (t < 64) {
        float a = b2[t];
        const float* w = &W2[(size_t)t * 128];
#pragma unroll 8
        for (int k = 0; k < 128; k++) a += z1[k] * w[k];
        z2[t] = fmaxf(a, 0.f);
    }
    __syncthreads();
    if (t < OO) {
        float a = b3[t];
        const float* w = &W3[(size_t)t * 64];
#pragma unroll
        for (int k = 0; k < 64; k++) a += z2[k] * w[k];
        logits[g * OO + t] = a;
    }
}

// ---------------- launch ----------------
extern "C" void kernel_launch(void* const* d_in, const int* in_sizes, int n_in,
                              void* d_out, int out_size) {
    const float* x   = (const float*)d_in[0];
    const void*  ei  = d_in[1];
    const void*  bat = d_in[2];
    const float* Wr1 = (const float*)d_in[3];
    const float* br1 = (const float*)d_in[4];
    const float* Wo1 = (const float*)d_in[5];
    const float* Wr2 = (const float*)d_in[6];
    const float* br2 = (const float*)d_in[7];
    const float* Wo2 = (const float*)d_in[8];
    const float* Wr3 = (const float*)d_in[9];
    const float* br3 = (const float*)d_in[10];
    const float* Wo3 = (const float*)d_in[11];
    const float* W1  = (const float*)d_in[12];
    const float* b1  = (const float*)d_in[13];
    const float* W2  = (const float*)d_in[14];
    const float* b2  = (const float*)d_in[15];
    const float* W3  = (const float*)d_in[16];
    const float* b3  = (const float*)d_in[17];

    int N = in_sizes[2];          // 50000
    int E = in_sizes[1] / 2;      // 800000

    float* out = (float*)d_out;
    float* logits   = out;                              // [G,O]
    float* nodeout  = out + GG * OO;                    // [N,H]
    float* graphout = out + GG * OO + (size_t)N * HH;   // [G,2H]

    // scratch pointers (device symbols resolved at compile time inside kernels)
    float* bufA;  cudaGetSymbolAddress((void**)&bufA, g_bufA);
    float* bufB;  cudaGetSymbolAddress((void**)&bufB, g_bufB);
    float* agg;   cudaGetSymbolAddress((void**)&agg, g_agg);

    detect_idx_kernel<<<1, 1>>>(ei, N);
    zero_misc_kernel<<<64, 256>>>(N);
    hist_edges_kernel<<<(E + 255) / 256, 256>>>(ei, E);
    hist_nodes_kernel<<<(N + 255) / 256, 256>>>(bat, N);
    scan_rows_kernel<<<1, 1024>>>(N);
    scatter_kernel<<<(E + 255) / 256, 256>>>(ei, E);
    graph_offsets_kernel<<<1, 32>>>();

    int gemmBlocks = (N + 127) / 128;

    // layer 1
    spmm_kernel<<<N, 128>>>(x, agg);
    gemm_dual_kernel<<<gemmBlocks, 256>>>(agg, x, Wr1, Wo1, br1, bufA, N);
    pool_kernel<<<GG, 128>>>(bufA);
    pool_accum_kernel<<<(GG * HH + 255) / 256, 256>>>();

    // layer 2
    spmm_kernel<<<N, 128>>>(bufA, agg);
    gemm_dual_kernel<<<gemmBlocks, 256>>>(agg, bufA, Wr2, Wo2, br2, bufB, N);
    pool_kernel<<<GG, 128>>>(bufB);
    pool_accum_kernel<<<(GG * HH + 255) / 256, 256>>>();

    // layer 3 -> node_embs straight into d_out
    spmm_kernel<<<N, 128>>>(bufB, agg);
    gemm_dual_kernel<<<gemmBlocks, 256>>>(agg, bufB, Wr3, Wo3, br3, nodeout, N);
    pool_kernel<<<GG, 128>>>(nodeout);
    pool_accum_kernel<<<(GG * HH + 255) / 256, 256>>>();

    mlp_kernel<<<GG, 128>>>(W1, b1, W2, b2, W3, b3, graphout, logits);
}

// round 3
// speedup vs baseline: 1.8607x; 1.8607x over previous
#include <cuda_runtime.h>
#include <cuda_bf16.h>
#include <cstdint>

// Problem constants (fixed by the dataset)
#define NN 50000
#define EE 800000
#define GG 64
#define HH 128
#define OO 10
#define PPB 8   // pooling partials per graph

// ---------------- static device scratch ----------------
__device__ float g_bufA[NN * HH];
__device__ float g_bufB[NN * HH];
__device__ float g_agg[NN * HH];
__device__ int   g_count[NN + 1];
__device__ int   g_rowptr[NN + 1];
__device__ int   g_cursor[NN];
__device__ int   g_col[EE];
__device__ int   g_gstart[GG + 1];
__device__ float g_inv[GG];
__device__ float g_pmax8[GG * PPB * HH];
__device__ float g_psum8[GG * PPB * HH];
__device__ float g_emb[GG * 2 * HH];
__device__ int   g_idx64;

// ---------------- small helpers ----------------
__device__ __forceinline__ uint32_t pack_bf16(float a, float b) {
    __nv_bfloat162 t = __floats2bfloat162_rn(a, b);
    return *(uint32_t*)&t;
}
__device__ __forceinline__ void ldsm4(uint32_t r[4], const void* p) {
    uint32_t a = (uint32_t)__cvta_generic_to_shared(p);
    asm volatile("ldmatrix.sync.aligned.m8n8.x4.shared.b16 {%0,%1,%2,%3}, [%4];"
                 : "=r"(r[0]), "=r"(r[1]), "=r"(r[2]), "=r"(r[3]) : "r"(a));
}
__device__ __forceinline__ void mma_bf16(float c[4], const uint32_t a[4],
                                         uint32_t b0, uint32_t b1) {
    asm volatile("mma.sync.aligned.m16n8k16.row.col.f32.bf16.bf16.f32 "
                 "{%0,%1,%2,%3}, {%4,%5,%6,%7}, {%8,%9}, {%0,%1,%2,%3};"
                 : "+f"(c[0]), "+f"(c[1]), "+f"(c[2]), "+f"(c[3])
                 : "r"(a[0]), "r"(a[1]), "r"(a[2]), "r"(a[3]), "r"(b0), "r"(b1));
}
// swizzled offset of 16B unit u (0..3) in row r (row = 64B of bf16)
__device__ __forceinline__ int swzoff(int r, int u) {
    return r * 64 + (((u ^ ((r >> 1) & 3)) & 3) << 4);
}

// ---------------- index dtype handling ----------------
__device__ __forceinline__ int idx_at(const void* p, long long i) {
    if (g_idx64) return (int)((const long long*)p)[i];
    return ((const int*)p)[i];
}

__global__ void detect_idx_kernel(const void* ei, int n) {
    const long long* p = (const long long*)ei;
    int ok = 1;
    for (int i = 0; i < 4; i++) {
        long long v = p[i];
        if (v < 0 || v >= (long long)n) ok = 0;
    }
    g_idx64 = ok;
}

// ---------------- setup kernels ----------------
__global__ void zero_misc_kernel(int n) {
    int stride = gridDim.x * blockDim.x;
    int i = blockIdx.x * blockDim.x + threadIdx.x;
    for (int k = i; k < n + 1; k += stride) g_count[k] = 0;
    for (int k = i; k < GG * 2 * HH; k += stride) g_emb[k] = 0.f;
}

__global__ void hist_edges_kernel(const void* ei, int E) {
    int e = blockIdx.x * blockDim.x + threadIdx.x;
    if (e < E) {
        int d = idx_at(ei, (long long)E + e);
        atomicAdd(&g_count[d], 1);
    }
}

__global__ void scan_rows_kernel(int n) {
    __shared__ int ssum[1024];
    int t = threadIdx.x;
    int C = (n + 1023) / 1024;
    int c0 = t * C;
    int c1 = min(c0 + C, n);
    int s = 0;
    for (int i = c0; i < c1; i++) s += g_count[i];
    ssum[t] = s;
    __syncthreads();
    for (int off = 1; off < 1024; off <<= 1) {
        int v = (t >= off) ? ssum[t - off] : 0;
        __syncthreads();
        ssum[t] += v;
        __syncthreads();
    }
    int run = (t == 0) ? 0 : ssum[t - 1];
    for (int i = c0; i < c1; i++) {
        g_rowptr[i] = run;
        g_cursor[i] = run;
        run += g_count[i];
    }
    if (c0 < n && c1 == n) g_rowptr[n] = run;
}

__global__ void scatter_kernel(const void* ei, int E) {
    int e = blockIdx.x * blockDim.x + threadIdx.x;
    if (e < E) {
        int d = idx_at(ei, (long long)E + e);
        int s = idx_at(ei, e);
        int pos = atomicAdd(&g_cursor[d], 1);
        g_col[pos] = s;
    }
}

// batch is sorted: graph boundaries via binary search (one small block)
__global__ void gstart_kernel(const void* batch, int n) {
    int g = threadIdx.x;
    if (g <= GG) {
        if (g == GG) {
            g_gstart[GG] = n;
        } else {
            int lo = 0, hi = n;
            while (lo < hi) {
                int mid = (lo + hi) >> 1;
                if (idx_at(batch, mid) < g) lo = mid + 1; else hi = mid;
            }
            g_gstart[g] = lo;
        }
    }
    __syncthreads();
    if (g < GG) {
        int c = g_gstart[g + 1] - g_gstart[g];
        g_inv[g] = 1.0f / (float)max(c, 1);
    }
}

// ---------------- SpMM: agg[d] = sum_{e: dst==d} h[src[e]] ----------------
// one warp per dst row; each lane owns a float4 (4 features)
__global__ void __launch_bounds__(256) spmm_kernel(const float* __restrict__ hin,
                                                   float* __restrict__ agg, int n) {
    int w = (blockIdx.x * blockDim.x + threadIdx.x) >> 5;
    int lane = threadIdx.x & 31;
    if (w >= n) return;
    const float4* h4 = (const float4*)hin;
    int s = g_rowptr[w];
    int e = g_rowptr[w + 1];
    float4 a0 = make_float4(0.f, 0.f, 0.f, 0.f);
    float4 a1 = make_float4(0.f, 0.f, 0.f, 0.f);
    float4 a2 = make_float4(0.f, 0.f, 0.f, 0.f);
    float4 a3 = make_float4(0.f, 0.f, 0.f, 0.f);
    int i = s;
    for (; i + 3 < e; i += 4) {
        int c0 = g_col[i + 0];
        int c1 = g_col[i + 1];
        int c2 = g_col[i + 2];
        int c3 = g_col[i + 3];
        float4 v0 = h4[(size_t)c0 * 32 + lane];
        float4 v1 = h4[(size_t)c1 * 32 + lane];
        float4 v2 = h4[(size_t)c2 * 32 + lane];
        float4 v3 = h4[(size_t)c3 * 32 + lane];
        a0.x += v0.x; a0.y += v0.y; a0.z += v0.z; a0.w += v0.w;
        a1.x += v1.x; a1.y += v1.y; a1.z += v1.z; a1.w += v1.w;
        a2.x += v2.x; a2.y += v2.y; a2.z += v2.z; a2.w += v2.w;
        a3.x += v3.x; a3.y += v3.y; a3.z += v3.z; a3.w += v3.w;
    }
    for (; i < e; i++) {
        float4 v = h4[(size_t)g_col[i] * 32 + lane];
        a0.x += v.x; a0.y += v.y; a0.z += v.z; a0.w += v.w;
    }
    float4 r;
    r.x = (a0.x + a1.x) + (a2.x + a3.x);
    r.y = (a0.y + a1.y) + (a2.y + a3.y);
    r.z = (a0.z + a1.z) + (a2.z + a3.z);
    r.w = (a0.w + a1.w) + (a2.w + a3.w);
    ((float4*)agg)[(size_t)w * 32 + lane] = r;
}

// ---------------- bf16-split dual GEMM via mma.sync + bias + relu ----------------
// C[i][j] = relu( sum_k A0[i][k]*B0[j][k] + A1[i][k]*B1[j][k] + bias[j] )
// CTA tile 128x128, K = 2*128 streamed in 8 chunks of 32.
// Split: x = hi(bf16) + lo(bf16); acc += Ah*Bh + Ah*Bl + Al*Bh  (ll dropped, ~2^-16)
__global__ void __launch_bounds__(256, 2) gemm_mma_kernel(
    const float* __restrict__ A0, const float* __restrict__ A1,
    const float* __restrict__ B0, const float* __restrict__ B1,
    const float* __restrict__ bias, float* __restrict__ C, int n)
{
    __shared__ __align__(16) uint8_t sAh[8192];
    __shared__ __align__(16) uint8_t sAl[8192];
    __shared__ __align__(16) uint8_t sBh[8192];
    __shared__ __align__(16) uint8_t sBl[8192];

    int tid = threadIdx.x;
    int lane = tid & 31;
    int wid = tid >> 5;
    int warpM = wid & 3;       // 4 along M
    int warpN = wid >> 2;      // 2 along N
    int row0 = blockIdx.x * 128;

    float acc[2][8][4];
#pragma unroll
    for (int mf = 0; mf < 2; mf++)
#pragma unroll
        for (int nf = 0; nf < 8; nf++)
#pragma unroll
            for (int q = 0; q < 4; q++) acc[mf][nf][q] = 0.f;

    int lr = tid >> 1;      // 0..127: row within tile
    int lh = tid & 1;       // which 16-float half of the 32-float chunk row

    for (int c = 0; c < 8; c++) {
        const float* A = (c < 4) ? A0 : A1;
        const float* B = (c < 4) ? B0 : B1;
        int kb = (c & 3) * 32 + lh * 16;
        __syncthreads();
        // ---- load + convert A rows ----
        {
            int grow = row0 + lr;
            float4 v0, v1, v2, v3;
            if (grow < n) {
                const float4* p = (const float4*)&A[(size_t)grow * 128 + kb];
                v0 = p[0]; v1 = p[1]; v2 = p[2]; v3 = p[3];
            } else {
                v0 = v1 = v2 = v3 = make_float4(0.f, 0.f, 0.f, 0.f);
            }
            float f[16] = {v0.x, v0.y, v0.z, v0.w, v1.x, v1.y, v1.z, v1.w,
                           v2.x, v2.y, v2.z, v2.w, v3.x, v3.y, v3.z, v3.w};
            float hi[16], lo[16];
#pragma unroll
            for (int q = 0; q < 16; q++) {
                hi[q] = __bfloat162float(__float2bfloat16_rn(f[q]));
                lo[q] = f[q] - hi[q];
            }
            uint4 uh0 = make_uint4(pack_bf16(hi[0], hi[1]), pack_bf16(hi[2], hi[3]),
                                   pack_bf16(hi[4], hi[5]), pack_bf16(hi[6], hi[7]));
            uint4 uh1 = make_uint4(pack_bf16(hi[8], hi[9]), pack_bf16(hi[10], hi[11]),
                                   pack_bf16(hi[12], hi[13]), pack_bf16(hi[14], hi[15]));
            uint4 ul0 = make_uint4(pack_bf16(lo[0], lo[1]), pack_bf16(lo[2], lo[3]),
                                   pack_bf16(lo[4], lo[5]), pack_bf16(lo[6], lo[7]));
            uint4 ul1 = make_uint4(pack_bf16(lo[8], lo[9]), pack_bf16(lo[10], lo[11]),
                                   pack_bf16(lo[12], lo[13]), pack_bf16(lo[14], lo[15]));
            *(uint4*)(sAh + swzoff(lr, lh * 2 + 0)) = uh0;
            *(uint4*)(sAh + swzoff(lr, lh * 2 + 1)) = uh1;
            *(uint4*)(sAl + swzoff(lr, lh * 2 + 0)) = ul0;
            *(uint4*)(sAl + swzoff(lr, lh * 2 + 1)) = ul1;
        }
        // ---- load + convert B rows (exactly 128, no guard) ----
        {
            const float4* p = (const float4*)&B[(size_t)lr * 128 + kb];
            float4 v0 = p[0], v1 = p[1], v2 = p[2], v3 = p[3];
            float f[16] = {v0.x, v0.y, v0.z, v0.w, v1.x, v1.y, v1.z, v1.w,
                           v2.x, v2.y, v2.z, v2.w, v3.x, v3.y, v3.z, v3.w};
            float hi[16], lo[16];
#pragma unroll
            for (int q = 0; q < 16; q++) {
                hi[q] = __bfloat162float(__float2bfloat16_rn(f[q]));
                lo[q] = f[q] - hi[q];
            }
            uint4 uh0 = make_uint4(pack_bf16(hi[0], hi[1]), pack_bf16(hi[2], hi[3]),
                                   pack_bf16(hi[4], hi[5]), pack_bf16(hi[6], hi[7]));
            uint4 uh1 = make_uint4(pack_bf16(hi[8], hi[9]), pack_bf16(hi[10], hi[11]),
                                   pack_bf16(hi[12], hi[13]), pack_bf16(hi[14], hi[15]));
            uint4 ul0 = make_uint4(pack_bf16(lo[0], lo[1]), pack_bf16(lo[2], lo[3]),
                                   pack_bf16(lo[4], lo[5]), pack_bf16(lo[6], lo[7]));
            uint4 ul1 = make_uint4(pack_bf16(lo[8], lo[9]), pack_bf16(lo[10], lo[11]),
                                   pack_bf16(lo[12], lo[13]), pack_bf16(lo[14], lo[15]));
            *(uint4*)(sBh + swzoff(lr, lh * 2 + 0)) = uh0;
            *(uint4*)(sBh + swzoff(lr, lh * 2 + 1)) = uh1;
            *(uint4*)(sBl + swzoff(lr, lh * 2 + 0)) = ul0;
            *(uint4*)(sBl + swzoff(lr, lh * 2 + 1)) = ul1;
        }
        __syncthreads();
        // ---- mma over the two k16 steps of this 32-wide chunk ----
#pragma unroll
        for (int s = 0; s < 2; s++) {
            uint32_t ah[2][4], al[2][4];
            int arow = warpM * 32 + (lane & 15);
            int au = 2 * s + (lane >> 4);
#pragma unroll
            for (int mf = 0; mf < 2; mf++) {
                ldsm4(ah[mf], sAh + swzoff(arow + mf * 16, au));
                ldsm4(al[mf], sAl + swzoff(arow + mf * 16, au));
            }
            int brow_off = (lane & 7) + ((lane >> 4) << 3);
            int bu = 2 * s + ((lane >> 3) & 1);
#pragma unroll
            for (int nf2 = 0; nf2 < 4; nf2++) {
                int brow = warpN * 64 + nf2 * 16 + brow_off;
                uint32_t bh[4], bl[4];
                ldsm4(bh, sBh + swzoff(brow, bu));
                ldsm4(bl, sBl + swzoff(brow, bu));
#pragma unroll
                for (int half = 0; half < 2; half++) {
                    int nf = nf2 * 2 + half;
#pragma unroll
                    for (int mf = 0; mf < 2; mf++) {
                        mma_bf16(acc[mf][nf], ah[mf], bh[half * 2], bh[half * 2 + 1]);
                        mma_bf16(acc[mf][nf], ah[mf], bl[half * 2], bl[half * 2 + 1]);
                        mma_bf16(acc[mf][nf], al[mf], bh[half * 2], bh[half * 2 + 1]);
                    }
                }
            }
        }
    }
    // ---- epilogue: bias + relu ----
#pragma unroll
    for (int mf = 0; mf < 2; mf++) {
        int row_lo = row0 + warpM * 32 + mf * 16 + (lane >> 2);
        int row_hi = row_lo + 8;
#pragma unroll
        for (int nf = 0; nf < 8; nf++) {
            int col = warpN * 64 + nf * 8 + (lane & 3) * 2;
            float b0 = bias[col], b1 = bias[col + 1];
            if (row_lo < n) {
                float2 o;
                o.x = fmaxf(acc[mf][nf][0] + b0, 0.f);
                o.y = fmaxf(acc[mf][nf][1] + b1, 0.f);
                *(float2*)&C[(size_t)row_lo * 128 + col] = o;
            }
            if (row_hi < n) {
                float2 o;
                o.x = fmaxf(acc[mf][nf][2] + b0, 0.f);
                o.y = fmaxf(acc[mf][nf][3] + b1, 0.f);
                *(float2*)&C[(size_t)row_hi * 128 + col] = o;
            }
        }
    }
}

// ---------------- pooling: PPB partial blocks per graph ----------------
__global__ void pool_kernel(const float* __restrict__ h) {
    int g = blockIdx.x / PPB;
    int p = blockIdx.x % PPB;
    int t = threadIdx.x;  // 128
    int n0 = g_gstart[g];
    int n1 = g_gstart[g + 1];
    int cnt = n1 - n0;
    int chunk = (cnt + PPB - 1) / PPB;
    int i0 = n0 + p * chunk;
    int i1 = min(i0 + chunk, n1);
    float mx0 = 0.f, mx1 = 0.f, sm0 = 0.f, sm1 = 0.f;
    int i = i0;
    for (; i + 1 < i1; i += 2) {
        float v0 = h[(size_t)i * HH + t];
        float v1 = h[(size_t)(i + 1) * HH + t];
        mx0 = fmaxf(mx0, v0);
        mx1 = fmaxf(mx1, v1);
        sm0 += v0;
        sm1 += v1;
    }
    if (i < i1) {
        float v = h[(size_t)i * HH + t];
        mx0 = fmaxf(mx0, v);
        sm0 += v;
    }
    g_pmax8[(g * PPB + p) * HH + t] = fmaxf(mx0, mx1);
    g_psum8[(g * PPB + p) * HH + t] = sm0 + sm1;
}

__global__ void pool_accum_kernel() {
    int idx = blockIdx.x * blockDim.x + threadIdx.x;  // GG*HH threads
    if (idx < GG * HH) {
        int g = idx >> 7;
        int f = idx & 127;
        float mx = 0.f, sm = 0.f;
#pragma unroll
        for (int p = 0; p < PPB; p++) {
            mx = fmaxf(mx, g_pmax8[(g * PPB + p) * HH + f]);
            sm += g_psum8[(g * PPB + p) * HH + f];
        }
        g_emb[g * 256 + f] += mx;
        g_emb[g * 256 + 128 + f] += sm * g_inv[g];
    }
}

// ---------------- MLP head + output of graph_emb ----------------
__global__ void mlp_kernel(const float* __restrict__ W1, const float* __restrict__ b1,
                           const float* __restrict__ W2, const float* __restrict__ b2,
                           const float* __restrict__ W3, const float* __restrict__ b3,
                           float* __restrict__ graphout, float* __restrict__ logits)
{
    __shared__ float in[256];
    __shared__ float z1[128];
    __shared__ float z2[64];
    int g = blockIdx.x;
    int t = threadIdx.x;  // 128
    in[t] = g_emb[g * 256 + t];
    in[t + 128] = g_emb[g * 256 + 128 + t];
    graphout[g * 256 + t] = in[t];
    graphout[g * 256 + 128 + t] = in[t + 128];
    __syncthreads();
    {
        float a = b1[t];
        const float* w = &W1[(size_t)t * 256];
#pragma unroll 8
        for (int k = 0; k < 256; k++) a += in[k] * w[k];
        z1[t] = fmaxf(a, 0.f);
    }
    __syncthreads();
    if (t < 64) {
        float a = b2[t];
        const float* w = &W2[(size_t)t * 128];
#pragma unroll 8
        for (int k = 0; k < 128; k++) a += z1[k] * w[k];
        z2[t] = fmaxf(a, 0.f);
    }
    __syncthreads();
    if (t < OO) {
        float a = b3[t];
        const float* w = &W3[(size_t)t * 64];
#pragma unroll
        for (int k = 0; k < 64; k++) a += z2[k] * w[k];
        logits[g * OO + t] = a;
    }
}

// ---------------- launch ----------------
extern "C" void kernel_launch(void* const* d_in, const int* in_sizes, int n_in,
                              void* d_out, int out_size) {
    const float* x   = (const float*)d_in[0];
    const void*  ei  = d_in[1];
    const void*  bat = d_in[2];
    const float* Wr1 = (const float*)d_in[3];
    const float* br1 = (const float*)d_in[4];
    const float* Wo1 = (const float*)d_in[5];
    const float* Wr2 = (const float*)d_in[6];
    const float* br2 = (const float*)d_in[7];
    const float* Wo2 = (const float*)d_in[8];
    const float* Wr3 = (const float*)d_in[9];
    const float* br3 = (const float*)d_in[10];
    const float* Wo3 = (const float*)d_in[11];
    const float* W1  = (const float*)d_in[12];
    const float* b1  = (const float*)d_in[13];
    const float* W2  = (const float*)d_in[14];
    const float* b2  = (const float*)d_in[15];
    const float* W3  = (const float*)d_in[16];
    const float* b3  = (const float*)d_in[17];

    int N = in_sizes[2];          // 50000
    int E = in_sizes[1] / 2;      // 800000

    float* out = (float*)d_out;
    float* logits   = out;                              // [G,O]
    float* nodeout  = out + GG * OO;                    // [N,H]
    float* graphout = out + GG * OO + (size_t)N * HH;   // [G,2H]

    float* bufA;  cudaGetSymbolAddress((void**)&bufA, g_bufA);
    float* bufB;  cudaGetSymbolAddress((void**)&bufB, g_bufB);
    float* agg;   cudaGetSymbolAddress((void**)&agg, g_agg);

    detect_idx_kernel<<<1, 1>>>(ei, N);
    zero_misc_kernel<<<64, 256>>>(N);
    hist_edges_kernel<<<(E + 255) / 256, 256>>>(ei, E);
    scan_rows_kernel<<<1, 1024>>>(N);
    scatter_kernel<<<(E + 255) / 256, 256>>>(ei, E);
    gstart_kernel<<<1, 128>>>(bat, N);

    int gemmBlocks = (N + 127) / 128;
    int spmmBlocks = (N + 7) / 8;

    // layer 1
    spmm_kernel<<<spmmBlocks, 256>>>(x, agg, N);
    gemm_mma_kernel<<<gemmBlocks, 256>>>(agg, x, Wr1, Wo1, br1, bufA, N);
    pool_kernel<<<GG * PPB, 128>>>(bufA);
    pool_accum_kernel<<<(GG * HH + 255) / 256, 256>>>();

    // layer 2
    spmm_kernel<<<spmmBlocks, 256>>>(bufA, agg, N);
    gemm_mma_kernel<<<gemmBlocks, 256>>>(agg, bufA, Wr2, Wo2, br2, bufB, N);
    pool_kernel<<<GG * PPB, 128>>>(bufB);
    pool_accum_kernel<<<(GG * HH + 255) / 256, 256>>>();

    // layer 3 -> node_embs straight into d_out
    spmm_kernel<<<spmmBlocks, 256>>>(bufB, agg, N);
    gemm_mma_kernel<<<gemmBlocks, 256>>>(agg, bufB, Wr3, Wo3, br3, nodeout, N);
    pool_kernel<<<GG * PPB, 128>>>(nodeout);
    pool_accum_kernel<<<(GG * HH + 255) / 256, 256>>>();

    mlp_kernel<<<GG, 128>>>(W1, b1, W2, b2, W3, b3, graphout, logits);
}

// round 4
// speedup vs baseline: 2.2504x; 1.2095x over previous
#include <cuda_runtime.h>
#include <cuda_bf16.h>
#include <cstdint>

// Problem constants (fixed by the dataset)
#define NN 50000
#define EE 800000
#define GG 64
#define HH 128
#define OO 10
#define PPB 8   // pooling partials per graph
#define SCB 256 // scan block size

// ---------------- static device scratch ----------------
__device__ float g_bufA[NN * HH];
__device__ float g_bufB[NN * HH];
__device__ float g_agg[NN * HH];
__device__ int   g_count[NN + 1];
__device__ int   g_rowptr[NN + 1];
__device__ int   g_cursor[NN];
__device__ int   g_col[EE];
__device__ int   g_bsum[(NN + SCB - 1) / SCB + 1];
__device__ int   g_boff[(NN + SCB - 1) / SCB + 1];
__device__ int   g_gstart[GG + 1];
__device__ float g_inv[GG];
__device__ float g_pmax8[GG * PPB * HH];
__device__ float g_psum8[GG * PPB * HH];
__device__ float g_emb[GG * 2 * HH];
__device__ int   g_idx64;

// ---------------- small helpers ----------------
__device__ __forceinline__ uint32_t pack_bf16(float a, float b) {
    __nv_bfloat162 t = __floats2bfloat162_rn(a, b);
    return *(uint32_t*)&t;
}
__device__ __forceinline__ void ldsm4(uint32_t r[4], const void* p) {
    uint32_t a = (uint32_t)__cvta_generic_to_shared(p);
    asm volatile("ldmatrix.sync.aligned.m8n8.x4.shared.b16 {%0,%1,%2,%3}, [%4];"
                 : "=r"(r[0]), "=r"(r[1]), "=r"(r[2]), "=r"(r[3]) : "r"(a));
}
__device__ __forceinline__ void mma_bf16(float c[4], const uint32_t a[4],
                                         uint32_t b0, uint32_t b1) {
    asm volatile("mma.sync.aligned.m16n8k16.row.col.f32.bf16.bf16.f32 "
                 "{%0,%1,%2,%3}, {%4,%5,%6,%7}, {%8,%9}, {%0,%1,%2,%3};"
                 : "+f"(c[0]), "+f"(c[1]), "+f"(c[2]), "+f"(c[3])
                 : "r"(a[0]), "r"(a[1]), "r"(a[2]), "r"(a[3]), "r"(b0), "r"(b1));
}
// swizzled offset of 16B unit u (0..3) in row r (row = 64B of bf16)
__device__ __forceinline__ int swzoff(int r, int u) {
    return r * 64 + (((u ^ ((r >> 1) & 3)) & 3) << 4);
}

// ---------------- index dtype handling ----------------
__device__ __forceinline__ int idx_at(const void* p, long long i) {
    if (g_idx64) return (int)((const long long*)p)[i];
    return ((const int*)p)[i];
}

__global__ void detect_idx_kernel(const void* ei, int n) {
    const long long* p = (const long long*)ei;
    int ok = 1;
    for (int i = 0; i < 4; i++) {
        long long v = p[i];
        if (v < 0 || v >= (long long)n) ok = 0;
    }
    g_idx64 = ok;
}

// ---------------- setup kernels ----------------
__global__ void zero_misc_kernel(int n) {
    int stride = gridDim.x * blockDim.x;
    int i = blockIdx.x * blockDim.x + threadIdx.x;
    for (int k = i; k < n + 1; k += stride) g_count[k] = 0;
    for (int k = i; k < GG * 2 * HH; k += stride) g_emb[k] = 0.f;
}

__global__ void hist_edges_kernel(const void* ei, int E) {
    int e = blockIdx.x * blockDim.x + threadIdx.x;
    if (e < E) {
        int d = idx_at(ei, (long long)E + e);
        atomicAdd(&g_count[d], 1);
    }
}

// ---------------- 3-phase parallel scan of g_count -> g_rowptr/g_cursor ----------------
__global__ void scan1_kernel(int n) {
    int i = blockIdx.x * SCB + threadIdx.x;
    int v = (i < n) ? g_count[i] : 0;
#pragma unroll
    for (int o = 16; o; o >>= 1) v += __shfl_down_sync(0xffffffffu, v, o);
    __shared__ int ws[SCB / 32];
    if ((threadIdx.x & 31) == 0) ws[threadIdx.x >> 5] = v;
    __syncthreads();
    if (threadIdx.x < SCB / 32) {
        int s = ws[threadIdx.x];
#pragma unroll
        for (int o = (SCB / 64); o; o >>= 1) s += __shfl_down_sync(0xffu, s, o);
        if (threadIdx.x == 0) g_bsum[blockIdx.x] = s;
    }
}

__global__ void scan2_kernel(int nb, int n) {
    // one block of 256 threads scans nb (<=256) block sums exclusively
    int t = threadIdx.x;
    int orig = (t < nb) ? g_bsum[t] : 0;
    int v = orig;
#pragma unroll
    for (int o = 1; o < 32; o <<= 1) {
        int u = __shfl_up_sync(0xffffffffu, v, o);
        if ((t & 31) >= o) v += u;
    }
    __shared__ int ws[8];
    if ((t & 31) == 31) ws[t >> 5] = v;
    __syncthreads();
    if (t < 8) {
        int s = ws[t];
#pragma unroll
        for (int o = 1; o < 8; o <<= 1) {
            int u = __shfl_up_sync(0xffu, s, o);
            if (t >= o) s += u;
        }
        ws[t] = s;
    }
    __syncthreads();
    int incl = v + ((t >= 32) ? ws[(t >> 5) - 1] : 0);
    if (t < nb) g_boff[t] = incl - orig;
    if (t == nb - 1) g_rowptr[n] = incl;
}

__global__ void scan3_kernel(int n) {
    int b = blockIdx.x;
    int t = threadIdx.x;
    int i = b * SCB + t;
    int orig = (i < n) ? g_count[i] : 0;
    int v = orig;
#pragma unroll
    for (int o = 1; o < 32; o <<= 1) {
        int u = __shfl_up_sync(0xffffffffu, v, o);
        if ((t & 31) >= o) v += u;
    }
    __shared__ int ws[SCB / 32];
    if ((t & 31) == 31) ws[t >> 5] = v;
    __syncthreads();
    if (t < SCB / 32) {
        int s = ws[t];
#pragma unroll
        for (int o = 1; o < SCB / 32; o <<= 1) {
            int u = __shfl_up_sync((1u << (SCB / 32)) - 1u, s, o);
            if (t >= o) s += u;
        }
        ws[t] = s;
    }
    __syncthreads();
    int incl = v + ((t >= 32) ? ws[(t >> 5) - 1] : 0);
    int excl = incl - orig + g_boff[b];
    if (i < n) {
        g_rowptr[i] = excl;
        g_cursor[i] = excl;
    }
}

__global__ void scatter_kernel(const void* ei, int E) {
    int e = blockIdx.x * blockDim.x + threadIdx.x;
    if (e < E) {
        int d = idx_at(ei, (long long)E + e);
        int s = idx_at(ei, e);
        int pos = atomicAdd(&g_cursor[d], 1);
        g_col[pos] = s;
    }
}

// batch is sorted: graph boundaries via binary search (one small block)
__global__ void gstart_kernel(const void* batch, int n) {
    int g = threadIdx.x;
    if (g <= GG) {
        if (g == GG) {
            g_gstart[GG] = n;
        } else {
            int lo = 0, hi = n;
            while (lo < hi) {
                int mid = (lo + hi) >> 1;
                if (idx_at(batch, mid) < g) lo = mid + 1; else hi = mid;
            }
            g_gstart[g] = lo;
        }
    }
    __syncthreads();
    if (g < GG) {
        int c = g_gstart[g + 1] - g_gstart[g];
        g_inv[g] = 1.0f / (float)max(c, 1);
    }
}

// ---------------- SpMM: agg[d] = sum_{e: dst==d} h[src[e]] ----------------
// one warp per dst row; each lane owns a float4 (4 features)
__global__ void __launch_bounds__(256) spmm_kernel(const float* __restrict__ hin,
                                                   float* __restrict__ agg, int n) {
    int w = (blockIdx.x * blockDim.x + threadIdx.x) >> 5;
    int lane = threadIdx.x & 31;
    if (w >= n) return;
    const float4* h4 = (const float4*)hin;
    int s = g_rowptr[w];
    int e = g_rowptr[w + 1];
    float4 a0 = make_float4(0.f, 0.f, 0.f, 0.f);
    float4 a1 = make_float4(0.f, 0.f, 0.f, 0.f);
    float4 a2 = make_float4(0.f, 0.f, 0.f, 0.f);
    float4 a3 = make_float4(0.f, 0.f, 0.f, 0.f);
    int i = s;
    for (; i + 3 < e; i += 4) {
        int c0 = g_col[i + 0];
        int c1 = g_col[i + 1];
        int c2 = g_col[i + 2];
        int c3 = g_col[i + 3];
        float4 v0 = h4[(size_t)c0 * 32 + lane];
        float4 v1 = h4[(size_t)c1 * 32 + lane];
        float4 v2 = h4[(size_t)c2 * 32 + lane];
        float4 v3 = h4[(size_t)c3 * 32 + lane];
        a0.x += v0.x; a0.y += v0.y; a0.z += v0.z; a0.w += v0.w;
        a1.x += v1.x; a1.y += v1.y; a1.z += v1.z; a1.w += v1.w;
        a2.x += v2.x; a2.y += v2.y; a2.z += v2.z; a2.w += v2.w;
        a3.x += v3.x; a3.y += v3.y; a3.z += v3.z; a3.w += v3.w;
    }
    for (; i < e; i++) {
        float4 v = h4[(size_t)g_col[i] * 32 + lane];
        a0.x += v.x; a0.y += v.y; a0.z += v.z; a0.w += v.w;
    }
    float4 r;
    r.x = (a0.x + a1.x) + (a2.x + a3.x);
    r.y = (a0.y + a1.y) + (a2.y + a3.y);
    r.z = (a0.z + a1.z) + (a2.z + a3.z);
    r.w = (a0.w + a1.w) + (a2.w + a3.w);
    ((float4*)agg)[(size_t)w * 32 + lane] = r;
}

// ---------------- bf16-split dual GEMM via mma.sync + bias + relu ----------------
// C[i][j] = relu( sum_k A0[i][k]*B0[j][k] + A1[i][k]*B1[j][k] + bias[j] )
// CTA tile 128x128, K = 2*128 streamed in 8 chunks of 32.
// Split: x = hi(bf16) + lo(bf16); acc += Ah*Bh + Ah*Bl + Al*Bh  (ll dropped, ~2^-16)
__global__ void __launch_bounds__(256, 2) gemm_mma_kernel(
    const float* __restrict__ A0, const float* __restrict__ A1,
    const float* __restrict__ B0, const float* __restrict__ B1,
    const float* __restrict__ bias, float* __restrict__ C, int n)
{
    __shared__ __align__(16) uint8_t sAh[8192];
    __shared__ __align__(16) uint8_t sAl[8192];
    __shared__ __align__(16) uint8_t sBh[8192];
    __shared__ __align__(16) uint8_t sBl[8192];

    int tid = threadIdx.x;
    int lane = tid & 31;
    int wid = tid >> 5;
    int warpM = wid & 3;       // 4 along M
    int warpN = wid >> 2;      // 2 along N
    int row0 = blockIdx.x * 128;

    float acc[2][8][4];
#pragma unroll
    for (int mf = 0; mf < 2; mf++)
#pragma unroll
        for (int nf = 0; nf < 8; nf++)
#pragma unroll
            for (int q = 0; q < 4; q++) acc[mf][nf][q] = 0.f;

    int lr = tid >> 1;      // 0..127: row within tile
    int lh = tid & 1;       // which 16-float half of the 32-float chunk row

    for (int c = 0; c < 8; c++) {
        const float* A = (c < 4) ? A0 : A1;
        const float* B = (c < 4) ? B0 : B1;
        int kb = (c & 3) * 32 + lh * 16;
        __syncthreads();
        // ---- load + convert A rows ----
        {
            int grow = row0 + lr;
            float4 v0, v1, v2, v3;
            if (grow < n) {
                const float4* p = (const float4*)&A[(size_t)grow * 128 + kb];
                v0 = p[0]; v1 = p[1]; v2 = p[2]; v3 = p[3];
            } else {
                v0 = v1 = v2 = v3 = make_float4(0.f, 0.f, 0.f, 0.f);
            }
            float f[16] = {v0.x, v0.y, v0.z, v0.w, v1.x, v1.y, v1.z, v1.w,
                           v2.x, v2.y, v2.z, v2.w, v3.x, v3.y, v3.z, v3.w};
            float hi[16], lo[16];
#pragma unroll
            for (int q = 0; q < 16; q++) {
                hi[q] = __bfloat162float(__float2bfloat16_rn(f[q]));
                lo[q] = f[q] - hi[q];
            }
            uint4 uh0 = make_uint4(pack_bf16(hi[0], hi[1]), pack_bf16(hi[2], hi[3]),
                                   pack_bf16(hi[4], hi[5]), pack_bf16(hi[6], hi[7]));
            uint4 uh1 = make_uint4(pack_bf16(hi[8], hi[9]), pack_bf16(hi[10], hi[11]),
                                   pack_bf16(hi[12], hi[13]), pack_bf16(hi[14], hi[15]));
            uint4 ul0 = make_uint4(pack_bf16(lo[0], lo[1]), pack_bf16(lo[2], lo[3]),
                                   pack_bf16(lo[4], lo[5]), pack_bf16(lo[6], lo[7]));
            uint4 ul1 = make_uint4(pack_bf16(lo[8], lo[9]), pack_bf16(lo[10], lo[11]),
                                   pack_bf16(lo[12], lo[13]), pack_bf16(lo[14], lo[15]));
            *(uint4*)(sAh + swzoff(lr, lh * 2 + 0)) = uh0;
            *(uint4*)(sAh + swzoff(lr, lh * 2 + 1)) = uh1;
            *(uint4*)(sAl + swzoff(lr, lh * 2 + 0)) = ul0;
            *(uint4*)(sAl + swzoff(lr, lh * 2 + 1)) = ul1;
        }
        // ---- load + convert B rows (exactly 128, no guard) ----
        {
            const float4* p = (const float4*)&B[(size_t)lr * 128 + kb];
            float4 v0 = p[0], v1 = p[1], v2 = p[2], v3 = p[3];
            float f[16] = {v0.x, v0.y, v0.z, v0.w, v1.x, v1.y, v1.z, v1.w,
                           v2.x, v2.y, v2.z, v2.w, v3.x, v3.y, v3.z, v3.w};
            float hi[16], lo[16];
#pragma unroll
            for (int q = 0; q < 16; q++) {
                hi[q] = __bfloat162float(__float2bfloat16_rn(f[q]));
                lo[q] = f[q] - hi[q];
            }
            uint4 uh0 = make_uint4(pack_bf16(hi[0], hi[1]), pack_bf16(hi[2], hi[3]),
                                   pack_bf16(hi[4], hi[5]), pack_bf16(hi[6], hi[7]));
            uint4 uh1 = make_uint4(pack_bf16(hi[8], hi[9]), pack_bf16(hi[10], hi[11]),
                                   pack_bf16(hi[12], hi[13]), pack_bf16(hi[14], hi[15]));
            uint4 ul0 = make_uint4(pack_bf16(lo[0], lo[1]), pack_bf16(lo[2], lo[3]),
                                   pack_bf16(lo[4], lo[5]), pack_bf16(lo[6], lo[7]));
            uint4 ul1 = make_uint4(pack_bf16(lo[8], lo[9]), pack_bf16(lo[10], lo[11]),
                                   pack_bf16(lo[12], lo[13]), pack_bf16(lo[14], lo[15]));
            *(uint4*)(sBh + swzoff(lr, lh * 2 + 0)) = uh0;
            *(uint4*)(sBh + swzoff(lr, lh * 2 + 1)) = uh1;
            *(uint4*)(sBl + swzoff(lr, lh * 2 + 0)) = ul0;
            *(uint4*)(sBl + swzoff(lr, lh * 2 + 1)) = ul1;
        }
        __syncthreads();
        // ---- mma over the two k16 steps of this 32-wide chunk ----
#pragma unroll
        for (int s = 0; s < 2; s++) {
            uint32_t ah[2][4], al[2][4];
            int arow = warpM * 32 + (lane & 15);
            int au = 2 * s + (lane >> 4);
#pragma unroll
            for (int mf = 0; mf < 2; mf++) {
                ldsm4(ah[mf], sAh + swzoff(arow + mf * 16, au));
                ldsm4(al[mf], sAl + swzoff(arow + mf * 16, au));
            }
            int brow_off = (lane & 7) + ((lane >> 4) << 3);
            int bu = 2 * s + ((lane >> 3) & 1);
#pragma unroll
            for (int nf2 = 0; nf2 < 4; nf2++) {
                int brow = warpN * 64 + nf2 * 16 + brow_off;
                uint32_t bh[4], bl[4];
                ldsm4(bh, sBh + swzoff(brow, bu));
                ldsm4(bl, sBl + swzoff(brow, bu));
#pragma unroll
                for (int half = 0; half < 2; half++) {
                    int nf = nf2 * 2 + half;
#pragma unroll
                    for (int mf = 0; mf < 2; mf++) {
                        mma_bf16(acc[mf][nf], ah[mf], bh[half * 2], bh[half * 2 + 1]);
                        mma_bf16(acc[mf][nf], ah[mf], bl[half * 2], bl[half * 2 + 1]);
                        mma_bf16(acc[mf][nf], al[mf], bh[half * 2], bh[half * 2 + 1]);
                    }
                }
            }
        }
    }
    // ---- epilogue: bias + relu ----
#pragma unroll
    for (int mf = 0; mf < 2; mf++) {
        int row_lo = row0 + warpM * 32 + mf * 16 + (lane >> 2);
        int row_hi = row_lo + 8;
#pragma unroll
        for (int nf = 0; nf < 8; nf++) {
            int col = warpN * 64 + nf * 8 + (lane & 3) * 2;
            float b0 = bias[col], b1 = bias[col + 1];
            if (row_lo < n) {
                float2 o;
                o.x = fmaxf(acc[mf][nf][0] + b0, 0.f);
                o.y = fmaxf(acc[mf][nf][1] + b1, 0.f);
                *(float2*)&C[(size_t)row_lo * 128 + col] = o;
            }
            if (row_hi < n) {
                float2 o;
                o.x = fmaxf(acc[mf][nf][2] + b0, 0.f);
                o.y = fmaxf(acc[mf][nf][3] + b1, 0.f);
                *(float2*)&C[(size_t)row_hi * 128 + col] = o;
            }
        }
    }
}

// ---------------- pooling: PPB partial blocks per graph ----------------
__global__ void pool_kernel(const float* __restrict__ h) {
    int g = blockIdx.x / PPB;
    int p = blockIdx.x % PPB;
    int t = threadIdx.x;  // 128
    int n0 = g_gstart[g];
    int n1 = g_gstart[g + 1];
    int cnt = n1 - n0;
    int chunk = (cnt + PPB - 1) / PPB;
    int i0 = n0 + p * chunk;
    int i1 = min(i0 + chunk, n1);
    float mx0 = 0.f, mx1 = 0.f, sm0 = 0.f, sm1 = 0.f;
    int i = i0;
    for (; i + 1 < i1; i += 2) {
        float v0 = h[(size_t)i * HH + t];
        float v1 = h[(size_t)(i + 1) * HH + t];
        mx0 = fmaxf(mx0, v0);
        mx1 = fmaxf(mx1, v1);
        sm0 += v0;
        sm1 += v1;
    }
    if (i < i1) {
        float v = h[(size_t)i * HH + t];
        mx0 = fmaxf(mx0, v);
        sm0 += v;
    }
    g_pmax8[(g * PPB + p) * HH + t] = fmaxf(mx0, mx1);
    g_psum8[(g * PPB + p) * HH + t] = sm0 + sm1;
}

__global__ void pool_accum_kernel() {
    int idx = blockIdx.x * blockDim.x + threadIdx.x;  // GG*HH threads
    if (idx < GG * HH) {
        int g = idx >> 7;
        int f = idx & 127;
        float mx = 0.f, sm = 0.f;
#pragma unroll
        for (int p = 0; p < PPB; p++) {
            mx = fmaxf(mx, g_pmax8[(g * PPB + p) * HH + f]);
            sm += g_psum8[(g * PPB + p) * HH + f];
        }
        g_emb[g * 256 + f] += mx;
        g_emb[g * 256 + 128 + f] += sm * g_inv[g];
    }
}

// ---------------- MLP head + output of graph_emb ----------------
__global__ void mlp_kernel(const float* __restrict__ W1, const float* __restrict__ b1,
                           const float* __restrict__ W2, const float* __restrict__ b2,
                           const float* __restrict__ W3, const float* __restrict__ b3,
                           float* __restrict__ graphout, float* __restrict__ logits)
{
    __shared__ float in[256];
    __shared__ float z1[128];
    __shared__ float z2[64];
    int g = blockIdx.x;
    int t = threadIdx.x;  // 128
    in[t] = g_emb[g * 256 + t];
    in[t + 128] = g_emb[g * 256 + 128 + t];
    graphout[g * 256 + t] = in[t];
    graphout[g * 256 + 128 + t] = in[t + 128];
    __syncthreads();
    {
        float a = b1[t];
        const float* w = &W1[(size_t)t * 256];
#pragma unroll 8
        for (int k = 0; k < 256; k++) a += in[k] * w[k];
        z1[t] = fmaxf(a, 0.f);
    }
    __syncthreads();
    if (t < 64) {
        float a = b2[t];
        const float* w = &W2[(size_t)t * 128];
#pragma unroll 8
        for (int k = 0; k < 128; k++) a += z1[k] * w[k];
        z2[t] = fmaxf(a, 0.f);
    }
    __syncthreads();
    if (t < OO) {
        float a = b3[t];
        const float* w = &W3[(size_t)t * 64];
#pragma unroll
        for (int k = 0; k < 64; k++) a += z2[k] * w[k];
        logits[g * OO + t] = a;
    }
}

// ---------------- launch ----------------
extern "C" void kernel_launch(void* const* d_in, const int* in_sizes, int n_in,
                              void* d_out, int out_size) {
    const float* x   = (const float*)d_in[0];
    const void*  ei  = d_in[1];
    const void*  bat = d_in[2];
    const float* Wr1 = (const float*)d_in[3];
    const float* br1 = (const float*)d_in[4];
    const float* Wo1 = (const float*)d_in[5];
    const float* Wr2 = (const float*)d_in[6];
    const float* br2 = (const float*)d_in[7];
    const float* Wo2 = (const float*)d_in[8];
    const float* Wr3 = (const float*)d_in[9];
    const float* br3 = (const float*)d_in[10];
    const float* Wo3 = (const float*)d_in[11];
    const float* W1  = (const float*)d_in[12];
    const float* b1  = (const float*)d_in[13];
    const float* W2  = (const float*)d_in[14];
    const float* b2  = (const float*)d_in[15];
    const float* W3  = (const float*)d_in[16];
    const float* b3  = (const float*)d_in[17];

    int N = in_sizes[2];          // 50000
    int E = in_sizes[1] / 2;      // 800000

    float* out = (float*)d_out;
    float* logits   = out;                              // [G,O]
    float* nodeout  = out + GG * OO;                    // [N,H]
    float* graphout = out + GG * OO + (size_t)N * HH;   // [G,2H]

    float* bufA;  cudaGetSymbolAddress((void**)&bufA, g_bufA);
    float* bufB;  cudaGetSymbolAddress((void**)&bufB, g_bufB);
    float* agg;   cudaGetSymbolAddress((void**)&agg, g_agg);

    int scanBlocks = (N + SCB - 1) / SCB;   // 196 for N=50000

    detect_idx_kernel<<<1, 1>>>(ei, N);
    zero_misc_kernel<<<64, 256>>>(N);
    hist_edges_kernel<<<(E + 255) / 256, 256>>>(ei, E);
    scan1_kernel<<<scanBlocks, SCB>>>(N);
    scan2_kernel<<<1, 256>>>(scanBlocks, N);
    scan3_kernel<<<scanBlocks, SCB>>>(N);
    scatter_kernel<<<(E + 255) / 256, 256>>>(ei, E);
    gstart_kernel<<<1, 128>>>(bat, N);

    int gemmBlocks = (N + 127) / 128;
    int spmmBlocks = (N + 7) / 8;

    // layer 1
    spmm_kernel<<<spmmBlocks, 256>>>(x, agg, N);
    gemm_mma_kernel<<<gemmBlocks, 256>>>(agg, x, Wr1, Wo1, br1, bufA, N);
    pool_kernel<<<GG * PPB, 128>>>(bufA);
    pool_accum_kernel<<<(GG * HH + 255) / 256, 256>>>();

    // layer 2
    spmm_kernel<<<spmmBlocks, 256>>>(bufA, agg, N);
    gemm_mma_kernel<<<gemmBlocks, 256>>>(agg, bufA, Wr2, Wo2, br2, bufB, N);
    pool_kernel<<<GG * PPB, 128>>>(bufB);
    pool_accum_kernel<<<(GG * HH + 255) / 256, 256>>>();

    // layer 3 -> node_embs straight into d_out
    spmm_kernel<<<spmmBlocks, 256>>>(bufB, agg, N);
    gemm_mma_kernel<<<gemmBlocks, 256>>>(agg, bufB, Wr3, Wo3, br3, nodeout, N);
    pool_kernel<<<GG * PPB, 128>>>(nodeout);
    pool_accum_kernel<<<(GG * HH + 255) / 256, 256>>>();

    mlp_kernel<<<GG, 128>>>(W1, b1, W2, b2, W3, b3, graphout, logits);
}